// round 14
// baseline (speedup 1.0000x reference)
#include <cuda_runtime.h>
#include <cuda_fp16.h>
#include <math.h>

#define NUM_L1 16
#define NUM_L2 8
#define IN_C   30             // 120 floats = 30 float4 chunks
#define N_VD   120
#define N_TD   28
#define WPB    8              // warps per block
#define APW    4              // atoms per warp

// output float offsets
#define O_VN   32
#define O_VD   56
#define O_TD   176

// vec pair table: word w packs pairs p=4w..4w+3, byte u = (i<<4)|j (triu order)
__device__ const unsigned int g_vp4[30] = {
    0x04030201u, 0x08070605u, 0x0C0B0A09u, 0x120F0E0Du,
    0x16151413u, 0x1A191817u, 0x1E1D1C1Bu, 0x2524231Fu,
    0x29282726u, 0x2D2C2B2Au, 0x35342F2Eu, 0x39383736u,
    0x3D3C3B3Au, 0x46453F3Eu, 0x4A494847u, 0x4E4D4C4Bu,
    0x5857564Fu, 0x5C5B5A59u, 0x675F5E5Du, 0x6B6A6968u,
    0x6F6E6D6Cu, 0x7B7A7978u, 0x7F7E7D7Cu, 0x8C8B8A89u,
    0x9A8F8E8Du, 0x9E9D9C9Bu, 0xADACAB9Fu, 0xBDBCAFAEu,
    0xCECDBFBEu, 0xEFDFDECFu
};
// tens pair table: p -> (i+16) | ((j+16)<<8)  (shuffle-ready lane indices)
__device__ const unsigned short g_tp16[28] = {
    0x1110,0x1210,0x1310,0x1410,0x1510,0x1610,0x1710,
    0x1211,0x1311,0x1411,0x1511,0x1611,0x1711,
    0x1312,0x1412,0x1512,0x1612,0x1712,
    0x1413,0x1513,0x1613,0x1713,
    0x1514,0x1614,0x1714,
    0x1615,0x1715,
    0x1716
};

struct LaneCtx {
    int c;          // source chunk for norm window
    int s;          // funnel shift (bits)
    bool b1;        // window high-select
    bool isv;       // vec lane?
    int vi0, vj0, vi1, vj1, vi2, vj2, vi3, vj3;   // vec pair lane indices
    int ti, tj;     // tens pair lane indices (pre-offset +16)
};

__device__ __forceinline__ void process_atom(const float4 v, float* __restrict__ orow,
                                             const int lane, const LaneCtx& L) {
    // ---- pack raw chunk for norm-operand transport ----
    __half2 hv01 = __floats2half2_rn(v.x, v.y);
    __half2 hv23 = __floats2half2_rn(v.z, v.w);
    const unsigned int r01 = *(const unsigned int*)&hv01;
    const unsigned int r23 = *(const unsigned int*)&hv23;

    const unsigned int A = __shfl_sync(0xffffffffu, r01, L.c);
    const unsigned int B = __shfl_sync(0xffffffffu, r23, L.c);
    const unsigned int C = __shfl_sync(0xffffffffu, r01, L.c + 1);
    const unsigned int D = __shfl_sync(0xffffffffu, r23, L.c + 1);

    // ---- scalars: direct STG.128 ----
    if (lane < 8) ((float4*)orow)[lane] = v;

    // ---- 5-half window select ----
    const unsigned int P = L.b1 ? B : A;
    const unsigned int Q = L.b1 ? C : B;
    const unsigned int R = L.b1 ? D : C;
    const unsigned int q01 = __funnelshift_r(P, Q, L.s);
    const unsigned int q23 = __funnelshift_r(Q, R, L.s);
    const unsigned int q4  = __funnelshift_r(R, R, L.s);

    const __half2 hc01 = *(const __half2*)&q01;
    const __half2 hc23 = *(const __half2*)&q23;
    float c0 = __low2float(hc01);
    float c1 = __high2float(hc01);
    float c2 = __low2float(hc23);
    float c3 = __high2float(hc23);
    float c4 = __low2float(*(const __half2*)&q4);
    if (L.isv) { c3 = 0.f; c4 = 0.f; }

    // ---- norm via rsqrt ----
    float ss = c0*c0 + c1*c1 + c2*c2 + c3*c3 + c4*c4;
    ss = fmaxf(ss, 1e-12f);
    const float inv = rsqrtf(ss);
    const float nrm = ss * inv;
    if (lane < NUM_L1 + NUM_L2)
        orow[O_VN + lane] = nrm;

    const float a4 = c4 * inv;
    __half2 p01 = __floats2half2_rn(c0 * inv, c1 * inv);
    __half2 p23 = __floats2half2_rn(c2 * inv, c3 * inv);
    const unsigned int u01 = *(const unsigned int*)&p01;
    const unsigned int u23 = *(const unsigned int*)&p23;

    // ---- vector pair dots: pairs p = 4*lane+u ----
    {
        float4 res;
        float* rr = (float*)&res;
        #pragma unroll
        for (int u = 0; u < 4; u++) {
            const int i = (u == 0) ? L.vi0 : (u == 1) ? L.vi1 : (u == 2) ? L.vi2 : L.vi3;
            const int j = (u == 0) ? L.vj0 : (u == 1) ? L.vj1 : (u == 2) ? L.vj2 : L.vj3;
            unsigned int qi01 = __shfl_sync(0xffffffffu, u01, i);
            unsigned int qi23 = __shfl_sync(0xffffffffu, u23, i);
            unsigned int qj01 = __shfl_sync(0xffffffffu, u01, j);
            unsigned int qj23 = __shfl_sync(0xffffffffu, u23, j);
            const __half2 acc = __hfma2(*(const __half2*)&qi23, *(const __half2*)&qj23,
                                        __hmul2(*(const __half2*)&qi01, *(const __half2*)&qj01));
            float d = __low2float(acc) + __high2float(acc);
            rr[u] = fminf(fmaxf(d, -1.0f), 1.0f);
        }
        if (lane < 30)
            *(float4*)(orow + O_VD + 4 * lane) = res;
    }

    // ---- tensor pair dots: p = lane (0..27) ----
    {
        unsigned int qi01 = __shfl_sync(0xffffffffu, u01, L.ti);
        unsigned int qi23 = __shfl_sync(0xffffffffu, u23, L.ti);
        float        qi4  = __shfl_sync(0xffffffffu, a4,  L.ti);
        unsigned int qj01 = __shfl_sync(0xffffffffu, u01, L.tj);
        unsigned int qj23 = __shfl_sync(0xffffffffu, u23, L.tj);
        float        qj4  = __shfl_sync(0xffffffffu, a4,  L.tj);
        const __half2 acc = __hfma2(*(const __half2*)&qi23, *(const __half2*)&qj23,
                                    __hmul2(*(const __half2*)&qi01, *(const __half2*)&qj01));
        if (lane < N_TD) {
            float d = fmaf(qi4, qj4, __low2float(acc) + __high2float(acc));
            orow[O_TD + lane] = fminf(fmaxf(d, -1.0f), 1.0f);
        }
    }
}

__global__ __launch_bounds__(32 * WPB, 4)
void invariant_extractor_kernel(const float4* __restrict__ h4,
                                float* __restrict__ out,
                                int n_atoms) {
    const int lane = threadIdx.x & 31;
    const int a0 = (blockIdx.x * WPB + (threadIdx.x >> 5)) * APW;
    if (a0 >= n_atoms) return;                  // warp-uniform
    const int nrem = n_atoms - a0;              // warp-uniform

    // ---- all rows' LDGs issued back-to-back (MLP = 4 per lane) ----
    const float4* row0 = h4 + (size_t)a0 * IN_C;
    float4 v0 = make_float4(0.f, 0.f, 0.f, 0.f);
    float4 v1 = v0, v2 = v0, v3 = v0;
    unsigned int w4 = 0u;
    if (lane < IN_C) {
        v0 = row0[lane];
        if (nrem > 1) v1 = row0[IN_C + lane];
        if (nrem > 2) v2 = row0[2 * IN_C + lane];
        if (nrem > 3) v3 = row0[3 * IN_C + lane];
        w4 = g_vp4[lane];
    }
    const int tp = (lane < N_TD) ? (int)g_tp16[lane] : 0x1010;

    // ---- atom-invariant lane context (shared by all atoms) ----
    LaneCtx L;
    L.isv = lane < NUM_L1;
    const int f0 = L.isv ? (32 + 3 * lane) : (80 + 5 * (lane - NUM_L1));
    L.c  = f0 >> 2;
    const int r = f0 & 3;
    L.b1 = (r & 2) != 0;
    L.s  = (r & 1) << 4;
    L.vi0 = (int)((w4 >>  4) & 15u);  L.vj0 = (int)( w4        & 15u);
    L.vi1 = (int)((w4 >> 12) & 15u);  L.vj1 = (int)((w4 >>  8) & 15u);
    L.vi2 = (int)((w4 >> 20) & 15u);  L.vj2 = (int)((w4 >> 16) & 15u);
    L.vi3 = (int)( w4 >> 28       );  L.vj3 = (int)((w4 >> 24) & 15u);
    L.ti = tp & 0xff;
    L.tj = tp >> 8;

    float* orow = out + (size_t)a0 * 204;
    process_atom(v0, orow, lane, L);
    if (nrem > 1) process_atom(v1, orow + 204, lane, L);
    if (nrem > 2) process_atom(v2, orow + 2 * 204, lane, L);
    if (nrem > 3) process_atom(v3, orow + 3 * 204, lane, L);
}

extern "C" void kernel_launch(void* const* d_in, const int* in_sizes, int n_in,
                              void* d_out, int out_size) {
    const float4* h = (const float4*)d_in[0];
    float* out = (float*)d_out;
    const int n_atoms = in_sizes[0] / 120;

    const int threads = 32 * WPB;
    const int atoms_per_block = WPB * APW;
    const int blocks = (n_atoms + atoms_per_block - 1) / atoms_per_block;
    invariant_extractor_kernel<<<blocks, threads>>>(h, out, n_atoms);
}

// round 15
// speedup vs baseline: 1.0396x; 1.0396x over previous
#include <cuda_runtime.h>
#include <cuda_fp16.h>
#include <math.h>

#define NUM_L1 16
#define NUM_L2 8
#define IN_C   30             // 120 floats = 30 float4 chunks
#define N_VD   120
#define N_TD   28
#define WPB    8              // warps per block
#define APW    3              // atoms per warp

// output float offsets
#define O_VN   32
#define O_VD   56
#define O_TD   176

// vec pair table: word w packs pairs p=4w..4w+3, byte u = (i<<4)|j (triu order)
__device__ const unsigned int g_vp4[30] = {
    0x04030201u, 0x08070605u, 0x0C0B0A09u, 0x120F0E0Du,
    0x16151413u, 0x1A191817u, 0x1E1D1C1Bu, 0x2524231Fu,
    0x29282726u, 0x2D2C2B2Au, 0x35342F2Eu, 0x39383736u,
    0x3D3C3B3Au, 0x46453F3Eu, 0x4A494847u, 0x4E4D4C4Bu,
    0x5857564Fu, 0x5C5B5A59u, 0x675F5E5Du, 0x6B6A6968u,
    0x6F6E6D6Cu, 0x7B7A7978u, 0x7F7E7D7Cu, 0x8C8B8A89u,
    0x9A8F8E8Du, 0x9E9D9C9Bu, 0xADACAB9Fu, 0xBDBCAFAEu,
    0xCECDBFBEu, 0xEFDFDECFu
};
// tens pair table: p -> (i+16) | ((j+16)<<8)  (shuffle-ready lane indices)
__device__ const unsigned short g_tp16[28] = {
    0x1110,0x1210,0x1310,0x1410,0x1510,0x1610,0x1710,
    0x1211,0x1311,0x1411,0x1511,0x1611,0x1711,
    0x1312,0x1412,0x1512,0x1612,0x1712,
    0x1413,0x1513,0x1613,0x1713,
    0x1514,0x1614,0x1714,
    0x1615,0x1715,
    0x1716
};

struct LaneCtx {
    int c;          // source chunk for norm window
    int s;          // funnel shift (bits)
    bool b1;        // window high-select
    bool isv;       // vec lane?
    int vi0, vj0, vi1, vj1, vi2, vj2, vi3, vj3;   // vec pair lane indices
    int ti, tj;     // tens pair lane indices (pre-offset +16)
};

__device__ __forceinline__ void process_atom(const float4 v, float* __restrict__ orow,
                                             const int lane, const LaneCtx& L) {
    // ---- pack raw chunk for norm-operand transport ----
    __half2 hv01 = __floats2half2_rn(v.x, v.y);
    __half2 hv23 = __floats2half2_rn(v.z, v.w);
    const unsigned int r01 = *(const unsigned int*)&hv01;
    const unsigned int r23 = *(const unsigned int*)&hv23;

    const unsigned int A = __shfl_sync(0xffffffffu, r01, L.c);
    const unsigned int B = __shfl_sync(0xffffffffu, r23, L.c);
    const unsigned int C = __shfl_sync(0xffffffffu, r01, L.c + 1);
    const unsigned int D = __shfl_sync(0xffffffffu, r23, L.c + 1);

    // ---- scalars: direct STG.128 ----
    if (lane < 8) ((float4*)orow)[lane] = v;

    // ---- 5-half window select ----
    const unsigned int P = L.b1 ? B : A;
    const unsigned int Q = L.b1 ? C : B;
    const unsigned int R = L.b1 ? D : C;
    const unsigned int q01 = __funnelshift_r(P, Q, L.s);
    const unsigned int q23 = __funnelshift_r(Q, R, L.s);
    const unsigned int q4  = __funnelshift_r(R, R, L.s);

    const __half2 hc01 = *(const __half2*)&q01;
    const __half2 hc23 = *(const __half2*)&q23;
    float c0 = __low2float(hc01);
    float c1 = __high2float(hc01);
    float c2 = __low2float(hc23);
    float c3 = __high2float(hc23);
    float c4 = __low2float(*(const __half2*)&q4);
    if (L.isv) { c3 = 0.f; c4 = 0.f; }

    // ---- norm via rsqrt ----
    float ss = c0*c0 + c1*c1 + c2*c2 + c3*c3 + c4*c4;
    ss = fmaxf(ss, 1e-12f);
    const float inv = rsqrtf(ss);
    const float nrm = ss * inv;
    if (lane < NUM_L1 + NUM_L2)
        orow[O_VN + lane] = nrm;

    const float a4 = c4 * inv;
    __half2 p01 = __floats2half2_rn(c0 * inv, c1 * inv);
    __half2 p23 = __floats2half2_rn(c2 * inv, c3 * inv);
    const unsigned int u01 = *(const unsigned int*)&p01;
    const unsigned int u23 = *(const unsigned int*)&p23;

    // ---- vector pair dots: pairs p = 4*lane+u ----
    {
        float4 res;
        float* rr = (float*)&res;
        #pragma unroll
        for (int u = 0; u < 4; u++) {
            const int i = (u == 0) ? L.vi0 : (u == 1) ? L.vi1 : (u == 2) ? L.vi2 : L.vi3;
            const int j = (u == 0) ? L.vj0 : (u == 1) ? L.vj1 : (u == 2) ? L.vj2 : L.vj3;
            unsigned int qi01 = __shfl_sync(0xffffffffu, u01, i);
            unsigned int qi23 = __shfl_sync(0xffffffffu, u23, i);
            unsigned int qj01 = __shfl_sync(0xffffffffu, u01, j);
            unsigned int qj23 = __shfl_sync(0xffffffffu, u23, j);
            const __half2 acc = __hfma2(*(const __half2*)&qi23, *(const __half2*)&qj23,
                                        __hmul2(*(const __half2*)&qi01, *(const __half2*)&qj01));
            float d = __low2float(acc) + __high2float(acc);
            rr[u] = fminf(fmaxf(d, -1.0f), 1.0f);
        }
        if (lane < 30)
            *(float4*)(orow + O_VD + 4 * lane) = res;
    }

    // ---- tensor pair dots: p = lane (0..27) ----
    {
        unsigned int qi01 = __shfl_sync(0xffffffffu, u01, L.ti);
        unsigned int qi23 = __shfl_sync(0xffffffffu, u23, L.ti);
        float        qi4  = __shfl_sync(0xffffffffu, a4,  L.ti);
        unsigned int qj01 = __shfl_sync(0xffffffffu, u01, L.tj);
        unsigned int qj23 = __shfl_sync(0xffffffffu, u23, L.tj);
        float        qj4  = __shfl_sync(0xffffffffu, a4,  L.tj);
        const __half2 acc = __hfma2(*(const __half2*)&qi23, *(const __half2*)&qj23,
                                    __hmul2(*(const __half2*)&qi01, *(const __half2*)&qj01));
        if (lane < N_TD) {
            float d = fmaf(qi4, qj4, __low2float(acc) + __high2float(acc));
            orow[O_TD + lane] = fminf(fmaxf(d, -1.0f), 1.0f);
        }
    }
}

__global__ __launch_bounds__(32 * WPB, 5)
void invariant_extractor_kernel(const float4* __restrict__ h4,
                                float* __restrict__ out,
                                int n_atoms) {
    const int lane = threadIdx.x & 31;
    const int a0 = (blockIdx.x * WPB + (threadIdx.x >> 5)) * APW;
    if (a0 >= n_atoms) return;                  // warp-uniform
    const int nrem = n_atoms - a0;              // warp-uniform

    // ---- all rows' LDGs issued back-to-back (MLP = 3 per lane) ----
    const float4* row0 = h4 + (size_t)a0 * IN_C;
    float4 v0 = make_float4(0.f, 0.f, 0.f, 0.f);
    float4 v1 = v0, v2 = v0;
    unsigned int w4 = 0u;
    if (lane < IN_C) {
        v0 = row0[lane];
        if (nrem > 1) v1 = row0[IN_C + lane];
        if (nrem > 2) v2 = row0[2 * IN_C + lane];
        w4 = g_vp4[lane];
    }
    const int tp = (lane < N_TD) ? (int)g_tp16[lane] : 0x1010;

    // ---- atom-invariant lane context (shared by all atoms) ----
    LaneCtx L;
    L.isv = lane < NUM_L1;
    const int f0 = L.isv ? (32 + 3 * lane) : (80 + 5 * (lane - NUM_L1));
    L.c  = f0 >> 2;
    const int r = f0 & 3;
    L.b1 = (r & 2) != 0;
    L.s  = (r & 1) << 4;
    L.vi0 = (int)((w4 >>  4) & 15u);  L.vj0 = (int)( w4        & 15u);
    L.vi1 = (int)((w4 >> 12) & 15u);  L.vj1 = (int)((w4 >>  8) & 15u);
    L.vi2 = (int)((w4 >> 20) & 15u);  L.vj2 = (int)((w4 >> 16) & 15u);
    L.vi3 = (int)( w4 >> 28       );  L.vj3 = (int)((w4 >> 24) & 15u);
    L.ti = tp & 0xff;
    L.tj = tp >> 8;

    float* orow = out + (size_t)a0 * 204;
    process_atom(v0, orow, lane, L);
    if (nrem > 1) process_atom(v1, orow + 204, lane, L);
    if (nrem > 2) process_atom(v2, orow + 2 * 204, lane, L);
}

extern "C" void kernel_launch(void* const* d_in, const int* in_sizes, int n_in,
                              void* d_out, int out_size) {
    const float4* h = (const float4*)d_in[0];
    float* out = (float*)d_out;
    const int n_atoms = in_sizes[0] / 120;

    const int threads = 32 * WPB;
    const int atoms_per_block = WPB * APW;
    const int blocks = (n_atoms + atoms_per_block - 1) / atoms_per_block;
    invariant_extractor_kernel<<<blocks, threads>>>(h, out, n_atoms);
}

// round 16
// speedup vs baseline: 1.0711x; 1.0303x over previous
#include <cuda_runtime.h>
#include <cuda_fp16.h>
#include <math.h>

#define NUM_L1 16
#define NUM_L2 8
#define IN_C   30             // 120 floats = 30 float4 chunks
#define N_TD   28
#define WPB    8              // warps per block
#define APW    3              // atoms per warp

// output float offsets
#define O_VN   32
#define O_VD   56
#define O_TD   176

// vec pair table: word w packs pairs p=4w..4w+3, byte u = (i<<4)|j (triu order)
__device__ const unsigned int g_vp4[30] = {
    0x04030201u, 0x08070605u, 0x0C0B0A09u, 0x120F0E0Du,
    0x16151413u, 0x1A191817u, 0x1E1D1C1Bu, 0x2524231Fu,
    0x29282726u, 0x2D2C2B2Au, 0x35342F2Eu, 0x39383736u,
    0x3D3C3B3Au, 0x46453F3Eu, 0x4A494847u, 0x4E4D4C4Bu,
    0x5857564Fu, 0x5C5B5A59u, 0x675F5E5Du, 0x6B6A6968u,
    0x6F6E6D6Cu, 0x7B7A7978u, 0x7F7E7D7Cu, 0x8C8B8A89u,
    0x9A8F8E8Du, 0x9E9D9C9Bu, 0xADACAB9Fu, 0xBDBCAFAEu,
    0xCECDBFBEu, 0xEFDFDECFu
};
// tens pair table: p -> (i+16) | ((j+16)<<8)  (shuffle-ready lane indices)
__device__ const unsigned short g_tp16[28] = {
    0x1110,0x1210,0x1310,0x1410,0x1510,0x1610,0x1710,
    0x1211,0x1311,0x1411,0x1511,0x1611,0x1711,
    0x1312,0x1412,0x1512,0x1612,0x1712,
    0x1413,0x1513,0x1613,0x1713,
    0x1514,0x1614,0x1714,
    0x1615,0x1715,
    0x1716
};

__device__ __forceinline__ void process_atom(const float4 v, float* __restrict__ orow,
                                             const int lane, const int c, const int s,
                                             const bool b1, const bool isv,
                                             const unsigned int w4, const int tp) {
    // ---- pack raw chunk for norm-operand transport ----
    __half2 hv01 = __floats2half2_rn(v.x, v.y);
    __half2 hv23 = __floats2half2_rn(v.z, v.w);
    const unsigned int r01 = *(const unsigned int*)&hv01;
    const unsigned int r23 = *(const unsigned int*)&hv23;

    const unsigned int A = __shfl_sync(0xffffffffu, r01, c);
    const unsigned int B = __shfl_sync(0xffffffffu, r23, c);
    const unsigned int C = __shfl_sync(0xffffffffu, r01, c + 1);
    const unsigned int D = __shfl_sync(0xffffffffu, r23, c + 1);

    // ---- scalars: direct STG.128 ----
    if (lane < 8) ((float4*)orow)[lane] = v;

    // ---- 5-half window select ----
    const unsigned int P = b1 ? B : A;
    const unsigned int Q = b1 ? C : B;
    const unsigned int R = b1 ? D : C;
    const unsigned int q01 = __funnelshift_r(P, Q, s);
    const unsigned int q23 = __funnelshift_r(Q, R, s);
    const unsigned int q4  = __funnelshift_r(R, R, s);

    const __half2 hc01 = *(const __half2*)&q01;
    const __half2 hc23 = *(const __half2*)&q23;
    float c0 = __low2float(hc01);
    float c1 = __high2float(hc01);
    float c2 = __low2float(hc23);
    float c3 = __high2float(hc23);
    float c4 = __low2float(*(const __half2*)&q4);
    if (isv) { c3 = 0.f; c4 = 0.f; }

    // ---- norm via rsqrt ----
    float ss = c0*c0 + c1*c1 + c2*c2 + c3*c3 + c4*c4;
    ss = fmaxf(ss, 1e-12f);
    const float inv = rsqrtf(ss);
    const float nrm = ss * inv;
    if (lane < NUM_L1 + NUM_L2)
        orow[O_VN + lane] = nrm;

    const float a4 = c4 * inv;
    __half2 p01 = __floats2half2_rn(c0 * inv, c1 * inv);
    __half2 p23 = __floats2half2_rn(c2 * inv, c3 * inv);
    const unsigned int u01 = *(const unsigned int*)&p01;
    const unsigned int u23 = *(const unsigned int*)&p23;

    // ---- vector pair dots: pairs p = 4*lane+u; indices decoded in-loop ----
    {
        float4 res;
        float* rr = (float*)&res;
        #pragma unroll
        for (int u = 0; u < 4; u++) {
            const int i = (int)((w4 >> (8 * u + 4)) & 15u);
            const int j = (int)((w4 >> (8 * u)) & 15u);
            unsigned int qi01 = __shfl_sync(0xffffffffu, u01, i);
            unsigned int qi23 = __shfl_sync(0xffffffffu, u23, i);
            unsigned int qj01 = __shfl_sync(0xffffffffu, u01, j);
            unsigned int qj23 = __shfl_sync(0xffffffffu, u23, j);
            const __half2 acc = __hfma2(*(const __half2*)&qi23, *(const __half2*)&qj23,
                                        __hmul2(*(const __half2*)&qi01, *(const __half2*)&qj01));
            float d = __low2float(acc) + __high2float(acc);
            rr[u] = fminf(fmaxf(d, -1.0f), 1.0f);
        }
        if (lane < 30)
            *(float4*)(orow + O_VD + 4 * lane) = res;
    }

    // ---- tensor pair dots: p = lane (0..27); indices decoded in-loop ----
    {
        const int ti = tp & 0xff;
        const int tj = tp >> 8;
        unsigned int qi01 = __shfl_sync(0xffffffffu, u01, ti);
        unsigned int qi23 = __shfl_sync(0xffffffffu, u23, ti);
        float        qi4  = __shfl_sync(0xffffffffu, a4,  ti);
        unsigned int qj01 = __shfl_sync(0xffffffffu, u01, tj);
        unsigned int qj23 = __shfl_sync(0xffffffffu, u23, tj);
        float        qj4  = __shfl_sync(0xffffffffu, a4,  tj);
        const __half2 acc = __hfma2(*(const __half2*)&qi23, *(const __half2*)&qj23,
                                    __hmul2(*(const __half2*)&qi01, *(const __half2*)&qj01));
        if (lane < N_TD) {
            float d = fmaf(qi4, qj4, __low2float(acc) + __high2float(acc));
            orow[O_TD + lane] = fminf(fmaxf(d, -1.0f), 1.0f);
        }
    }
}

__global__ __launch_bounds__(32 * WPB, 6)
void invariant_extractor_kernel(const float4* __restrict__ h4,
                                float* __restrict__ out,
                                int n_atoms) {
    const int lane = threadIdx.x & 31;
    const int a0 = (blockIdx.x * WPB + (threadIdx.x >> 5)) * APW;
    if (a0 >= n_atoms) return;                  // warp-uniform
    const int nrem = n_atoms - a0;              // warp-uniform

    // ---- all rows' LDGs issued back-to-back (MLP = 3 per lane) ----
    const float4* row0 = h4 + (size_t)a0 * IN_C;
    float4 v0 = make_float4(0.f, 0.f, 0.f, 0.f);
    float4 v1 = v0, v2 = v0;
    unsigned int w4 = 0u;
    if (lane < IN_C) {
        v0 = row0[lane];
        if (nrem > 1) v1 = row0[IN_C + lane];
        if (nrem > 2) v2 = row0[2 * IN_C + lane];
        w4 = g_vp4[lane];
    }
    const int tp = (lane < N_TD) ? (int)g_tp16[lane] : 0x1010;

    // ---- atom-invariant lane geometry (packed; ~5 regs total) ----
    const bool isv = lane < NUM_L1;
    const int f0 = isv ? (32 + 3 * lane) : (80 + 5 * (lane - NUM_L1));
    const int c  = f0 >> 2;
    const int r  = f0 & 3;
    const bool b1 = (r & 2) != 0;
    const int s   = (r & 1) << 4;

    float* orow = out + (size_t)a0 * 204;
    process_atom(v0, orow, lane, c, s, b1, isv, w4, tp);
    if (nrem > 1) process_atom(v1, orow + 204, lane, c, s, b1, isv, w4, tp);
    if (nrem > 2) process_atom(v2, orow + 2 * 204, lane, c, s, b1, isv, w4, tp);
}

extern "C" void kernel_launch(void* const* d_in, const int* in_sizes, int n_in,
                              void* d_out, int out_size) {
    const float4* h = (const float4*)d_in[0];
    float* out = (float*)d_out;
    const int n_atoms = in_sizes[0] / 120;

    const int threads = 32 * WPB;
    const int atoms_per_block = WPB * APW;
    const int blocks = (n_atoms + atoms_per_block - 1) / atoms_per_block;
    invariant_extractor_kernel<<<blocks, threads>>>(h, out, n_atoms);
}